// round 13
// baseline (speedup 1.0000x reference)
#include <cuda_runtime.h>

// ---------------------------------------------------------------------------
// GRU (511 steps) + BCE via mma.sync m16n8k8 tf32. Persistent, 256 CTAs
// (16 batch x 16 unit groups), 2 CTAs/SM.
// CTA GEMM/step: [16 rows] x [64 cols: r16|z16|nh16|ni16] x K=384.
// R13: warp = one 8-col n-tile over FULL K -> no K-reduction, 2 syncs/step,
// per-warp release (counter target t*128). r/z warps: x-ktiles pre-wait +
// h-ktiles post; nh warps h-only; ni warps x-only (all pre-wait) + loss.
// h exchanged tf32-pre-rounded; fp32 state carried in a register (hp).
// ---------------------------------------------------------------------------

#define BATCH 256
#define IN_DIM 128
#define HID 256
#define STEPS 511
#define NCTA 256
#define NTHREADS 256
#define ASTR 388
#define WSTR 388

#define OFF_W   0                         // 48 x 388 = 18624
#define OFF_A   18624                     // 16 x 388 = 6208
#define OFF_G   24832                     // 16 x 68 = 1088
#define OFF_SB  25920                     // 64
#define OFF_WD  25984                     // 256
#define SMEM_FLOATS 26240
#define SMEM_BYTES (SMEM_FLOATS * 4)      // 104960

typedef unsigned int u32;

__device__ float g_h[2][BATCH * HID];                    // tf32-pre-rounded h
__device__ float g_xr[(size_t)STEPS * BATCH * IN_DIM];   // tf32-pre-rounded x
__device__ unsigned g_arr[16 * 32];

__device__ __forceinline__ float tf32r(float f) {
    u32 u;
    asm("cvt.rna.tf32.f32 %0, %1;" : "=r"(u) : "f"(f));
    return __uint_as_float(u);
}

__global__ void gru_init_kernel(float* out, const float* __restrict__ x) {
    int i = blockIdx.x * blockDim.x + threadIdx.x;
    int stride = gridDim.x * blockDim.x;
    if (i == 0) out[0] = 0.0f;
    if (i < 16 * 32) g_arr[i] = 0u;
    for (int j = i; j < BATCH * HID; j += stride)
        g_h[0][j] = 0.0f;
    const float4* x4 = (const float4*)x;
    float4* r4 = (float4*)g_xr;
    int n4 = (int)((size_t)STEPS * BATCH * IN_DIM / 4);
    for (int j = i; j < n4; j += stride) {
        float4 v = x4[j];
        v.x = tf32r(v.x); v.y = tf32r(v.y); v.z = tf32r(v.z); v.w = tf32r(v.w);
        r4[j] = v;
    }
}

__device__ __forceinline__ void mma8(float* c, u32 a0, u32 a1, u32 a2, u32 a3,
                                     u32 b0, u32 b1) {
    asm volatile(
        "mma.sync.aligned.m16n8k8.row.col.f32.tf32.tf32.f32 "
        "{%0,%1,%2,%3}, {%4,%5,%6,%7}, {%8,%9}, {%0,%1,%2,%3};"
        : "+f"(c[0]), "+f"(c[1]), "+f"(c[2]), "+f"(c[3])
        : "r"(a0), "r"(a1), "r"(a2), "r"(a3), "r"(b0), "r"(b1));
}
__device__ __forceinline__ float sigf(float v) { return 1.0f / (1.0f + __expf(-v)); }
__device__ __forceinline__ unsigned ld_acq(const unsigned* p) {
    unsigned v;
    asm volatile("ld.acquire.gpu.global.u32 %0, [%1];" : "=r"(v) : "l"(p) : "memory");
    return v;
}
__device__ __forceinline__ void red_release(unsigned* p) {
    asm volatile("red.release.gpu.global.add.u32 [%0], %1;" :: "l"(p), "r"(1u) : "memory");
}

__global__ __launch_bounds__(NTHREADS, 2)
void gru_main_kernel(const float* __restrict__ x, const float* __restrict__ gt,
                     const float* __restrict__ W_ih, const float* __restrict__ W_hh,
                     const float* __restrict__ b_ih, const float* __restrict__ b_hh,
                     const float* __restrict__ W_dec, const float* __restrict__ b_dec,
                     float* __restrict__ out)
{
    extern __shared__ float smem[];
    float* sW  = smem + OFF_W;
    float* sA  = smem + OFF_A;
    float* gb  = smem + OFF_G;
    float* sb  = smem + OFF_SB;
    float* sWd = smem + OFF_WD;

    const int tid  = threadIdx.x;
    const int cb   = blockIdx.x & 15;
    const int cu   = blockIdx.x >> 4;
    const int B0   = cb * 16;
    const int U0   = cu * 16;

    const int lane = tid & 31;
    const int wid  = tid >> 5;
    const int nt   = wid;                 // n-tile: cols 8nt..8nt+7
    const int gate = nt >> 1;             // 0 r, 1 z, 2 nh, 3 ni
    const int lg   = lane >> 2;
    const int lt   = lane & 3;

    // ---- persistent W (tf32-rounded), biases, W_dec; zero sA h-region
    for (int idx = tid; idx < 48 * 384; idx += NTHREADS) {
        int gr = idx / 384, k = idx - gr * 384;
        int g = gr >> 4, uu = gr & 15, grow = g * HID + U0 + uu;
        float v = (k < HID) ? W_hh[grow * HID + k] : W_ih[grow * IN_DIM + (k - HID)];
        sW[gr * WSTR + k] = tf32r(v);
    }
    for (int i = tid; i < 16 * 256; i += NTHREADS) {
        int r = i >> 8, c0 = i & 255;
        sA[r * ASTR + c0] = 0.0f;                       // h(0) = 0
    }
    if (tid < 16) {
        sb[tid]      = b_ih[U0 + tid] + b_hh[U0 + tid];              // r
        sb[16 + tid] = b_ih[HID + U0 + tid] + b_hh[HID + U0 + tid];  // z
        sb[32 + tid] = b_hh[2 * HID + U0 + tid];                     // n (h side)
        sb[48 + tid] = b_ih[2 * HID + U0 + tid];                     // n (x side)
    }
    sWd[tid] = W_dec[tid];
    {   // stage x(0) (pre-rounded)
        int row = tid >> 4;
        const float4* src = (const float4*)(g_xr + (size_t)(B0 + row) * IN_DIM);
        #pragma unroll
        for (int q = 0; q < 2; ++q) {
            int k4 = (tid & 15) + 16 * q;
            *(float4*)(sA + row * ASTR + HID + 4 * k4) = __ldg(src + k4);
        }
    }
    __syncthreads();

    const float bdec = b_dec[0];
    float loss_local = 0.0f;
    int p = 0;
    unsigned* cnt = &g_arr[cb * 32];

    // fragment pointers
    const float* aP = sA + lg * ASTR + lt;
    const float* bP;
    {
        int ncol = 8 * nt + lg;
        int prow = (ncol < 48) ? ncol : ncol - 16;      // ni cols 48-63 -> rows 32-47
        bP = sW + prow * WSTR + lt;
    }
    const int erow = tid >> 4, eu = tid & 15;           // epilogue element
    float hp = 0.0f;                                    // fp32 h state, in-register
    float* gbW = gb + lg * 68 + 8 * nt + 2 * lt;

    for (int t = 0; t < STEPS; ++t) {
        float c[4] = {0.f, 0.f, 0.f, 0.f};

        // ---- x-part MMA (kt = 32..47) BEFORE the wait (r, z, ni warps)
        if (gate != 2) {
            #pragma unroll
            for (int kt = 32; kt < 48; ++kt) {
                const float* a = aP + 8 * kt;
                const float* b = bP + 8 * kt;
                mma8(c, __float_as_uint(a[0]), __float_as_uint(a[8 * ASTR]),
                        __float_as_uint(a[4]), __float_as_uint(a[4 + 8 * ASTR]),
                        __float_as_uint(b[0]), __float_as_uint(b[4]));
            }
        }

        // ---- per-warp wait for h(t) (all 128 producer warps of the group)
        if (t > 0) {
            if (lane == 0) {
                unsigned target = (unsigned)t * 128u;
                while (ld_acq(cnt) < target) __nanosleep(20);
            }
            __syncwarp();
        }

        // ---- stage h(t): each warp its 2 rows (pure tf32 copy)
        {
            int row = 2 * wid + (lane >> 4);
            const float4* src = (const float4*)(g_h[p] + (B0 + row) * HID);
            #pragma unroll
            for (int q = 0; q < 4; ++q) {
                int k4 = (lane & 15) + 16 * q;
                *(float4*)(sA + row * ASTR + 4 * k4) = __ldcg(src + k4);
            }
        }
        __syncthreads();                                 // sync1

        // ---- loss for h(t) on warp 7 (ni warp: MMA already done pre-wait)
        if (wid == 7 && t > 0) {
            const float* hr = sA + cu * ASTR;
            float s = 0.0f;
            #pragma unroll
            for (int q = 0; q < 8; ++q) {
                int k = lane + 32 * q;
                s += hr[k] * sWd[k];
            }
            #pragma unroll
            for (int sft = 16; sft > 0; sft >>= 1)
                s += __shfl_down_sync(0xffffffffu, s, sft);
            if (lane == 0) {
                float l = s + bdec;
                float g = gt[t * BATCH + B0 + cu];
                loss_local += fmaxf(l, 0.0f) + log1pf(__expf(-fabsf(l))) - g * l;
            }
        }

        // ---- h-part MMA (kt = 0..31) for r, z, nh warps
        if (nt < 6) {
            #pragma unroll
            for (int kt = 0; kt < 32; ++kt) {
                const float* a = aP + 8 * kt;
                const float* b = bP + 8 * kt;
                mma8(c, __float_as_uint(a[0]), __float_as_uint(a[8 * ASTR]),
                        __float_as_uint(a[4]), __float_as_uint(a[4 + 8 * ASTR]),
                        __float_as_uint(b[0]), __float_as_uint(b[4]));
            }
        }

        // ---- write finished gate columns (no K-reduction needed)
        *(float2*)(gbW)          = make_float2(c[0], c[1]);
        *(float2*)(gbW + 8 * 68) = make_float2(c[2], c[3]);

        // ---- restage x(t+1) (pure copy; x-region dead after pre-wait MMAs)
        if (t + 1 < STEPS) {
            int row = tid >> 4;
            const float4* src = (const float4*)(g_xr + ((size_t)(t + 1) * BATCH + B0 + row) * IN_DIM);
            #pragma unroll
            for (int q = 0; q < 2; ++q) {
                int k4 = (tid & 15) + 16 * q;
                *(float4*)(sA + row * ASTR + HID + 4 * k4) = __ldg(src + k4);
            }
        }
        __syncthreads();                                 // sync2

        // ---- epilogue: one h element per thread; per-warp release
        {
            float rr = gb[erow * 68 + eu];
            float zz = gb[erow * 68 + 16 + eu];
            float hh = gb[erow * 68 + 32 + eu];
            float ii = gb[erow * 68 + 48 + eu];
            float rv = sigf(rr + sb[eu]);
            float zv = sigf(zz + sb[16 + eu]);
            float pre = ii + sb[48 + eu] + rv * (hh + sb[32 + eu]);
            float nv = 2.0f * sigf(2.0f * pre) - 1.0f;               // tanh
            float hn = nv + zv * (hp - nv);
            hp = hn;                                                  // carry fp32
            g_h[p ^ 1][(B0 + erow) * HID + U0 + eu] = tf32r(hn);      // publish tf32
        }
        __syncwarp();
        if (lane == 0) red_release(cnt);                 // warp's 2 rows published
        p ^= 1;
    }

    // ---- final loss: h(511) (tf32), gt[511]
    if (tid == 0) {
        while (ld_acq(cnt) < (unsigned)STEPS * 128u) __nanosleep(20);
    }
    __syncthreads();
    if (tid < 32) {
        const float* hr = g_h[p] + (B0 + cu) * HID;
        float s = 0.0f;
        #pragma unroll
        for (int q = 0; q < 8; ++q) {
            int k = lane + 32 * q;
            s += __ldcg(hr + k) * sWd[k];
        }
        #pragma unroll
        for (int sft = 16; sft > 0; sft >>= 1)
            s += __shfl_down_sync(0xffffffffu, s, sft);
        if (lane == 0) {
            float l = s + bdec;
            float g = gt[(size_t)STEPS * BATCH + B0 + cu];
            loss_local += fmaxf(l, 0.0f) + log1pf(__expf(-fabsf(l))) - g * l;
        }
    }
    if (tid == 0 || (wid == 7 && lane == 0)) atomicAdd(out, loss_local);
}

extern "C" void kernel_launch(void* const* d_in, const int* in_sizes, int n_in,
                              void* d_out, int out_size) {
    const float* x     = (const float*)d_in[0];
    const float* gt    = (const float*)d_in[1];
    const float* W_ih  = (const float*)d_in[2];
    const float* W_hh  = (const float*)d_in[3];
    const float* b_ih  = (const float*)d_in[4];
    const float* b_hh  = (const float*)d_in[5];
    const float* W_dec = (const float*)d_in[6];
    const float* b_dec = (const float*)d_in[7];
    float* out = (float*)d_out;

    cudaFuncSetAttribute(gru_main_kernel,
                         cudaFuncAttributeMaxDynamicSharedMemorySize, SMEM_BYTES);

    gru_init_kernel<<<1024, 256>>>(out, x);
    gru_main_kernel<<<NCTA, NTHREADS, SMEM_BYTES>>>(
        x, gt, W_ih, W_hh, b_ih, b_hh, W_dec, b_dec, out);
}

// round 14
// speedup vs baseline: 1.3382x; 1.3382x over previous
#include <cuda_runtime.h>
#include <cuda_bf16.h>

// ---------------------------------------------------------------------------
// GRU (511 steps) + BCE via mma.sync m16n8k16 bf16 (fp32 accum). Persistent,
// 256 CTAs (16 batch x 16 unit groups), 2 CTAs/SM.
// CTA GEMM/step: [16 rows] x [64 cols: r16|z16|nh16|ni16] x K=384 (24 k16).
// Warps: nq = wid&3 (16-col quarter), kq = wid>>2 (k16 parity).
// R14: bf16 fragments, B (weights) hoisted into registers for ALL steps,
// tanh.approx epilogue. fp32 recurrence state carried per-thread (hp);
// h exchanged as bf16. x pre-converted to bf16 at init (g_xb).
// ---------------------------------------------------------------------------

#define BATCH 256
#define IN_DIM 128
#define HID 256
#define STEPS 511
#define NCTA 256
#define NTHREADS 256

// byte offsets; W/A rows have u32-stride 196 (=392 bf16, 784B): bank-safe
#define OFF_W   0                         // 48 x 784
#define OFF_A   37632                     // 16 x 784
#define OFF_SCR 50176                     // 4 x 288 floats
#define OFF_G   54784                     // 16 x 68 floats
#define OFF_SB  59136                     // 64 floats
#define OFF_WD  59392                     // 256 floats
#define SMEM_BYTES 60416

typedef unsigned int u32;
typedef __nv_bfloat16 bf16;

__device__ bf16 g_hb[2][BATCH * HID];
__device__ bf16 g_xb[(size_t)STEPS * BATCH * IN_DIM];
__device__ unsigned g_arr[16 * 32];

__global__ void gru_init_kernel(float* out, const float* __restrict__ x) {
    int i = blockIdx.x * blockDim.x + threadIdx.x;
    int stride = gridDim.x * blockDim.x;
    if (i == 0) out[0] = 0.0f;
    if (i < 512) g_arr[i] = 0u;
    u32* h0 = (u32*)g_hb[0];
    for (int j = i; j < BATCH * HID / 2; j += stride) h0[j] = 0u;
    const float2* x2 = (const float2*)x;
    u32* xb = (u32*)g_xb;
    int n2 = (int)((size_t)STEPS * BATCH * IN_DIM / 2);
    for (int j = i; j < n2; j += stride) {
        float2 v = x2[j];
        u32 r;
        asm("cvt.rn.bf16x2.f32 %0, %1, %2;" : "=r"(r) : "f"(v.y), "f"(v.x));
        xb[j] = r;
    }
}

__device__ __forceinline__ void mma16(float* c, u32 a0, u32 a1, u32 a2, u32 a3,
                                      u32 b0, u32 b1) {
    asm volatile(
        "mma.sync.aligned.m16n8k16.row.col.f32.bf16.bf16.f32 "
        "{%0,%1,%2,%3}, {%4,%5,%6,%7}, {%8,%9}, {%0,%1,%2,%3};"
        : "+f"(c[0]), "+f"(c[1]), "+f"(c[2]), "+f"(c[3])
        : "r"(a0), "r"(a1), "r"(a2), "r"(a3), "r"(b0), "r"(b1));
}
__device__ __forceinline__ float tanhap(float v) {
    float r;
    asm("tanh.approx.f32 %0, %1;" : "=f"(r) : "f"(v));
    return r;
}
__device__ __forceinline__ float sigap(float v) {
    return 0.5f * tanhap(0.5f * v) + 0.5f;
}
__device__ __forceinline__ unsigned ld_acq(const unsigned* p) {
    unsigned v;
    asm volatile("ld.acquire.gpu.global.u32 %0, [%1];" : "=r"(v) : "l"(p) : "memory");
    return v;
}
__device__ __forceinline__ void red_release(unsigned* p) {
    asm volatile("red.release.gpu.global.add.u32 [%0], %1;" :: "l"(p), "r"(1u) : "memory");
}

__global__ __launch_bounds__(NTHREADS, 2)
void gru_main_kernel(const float* __restrict__ x, const float* __restrict__ gt,
                     const float* __restrict__ W_ih, const float* __restrict__ W_hh,
                     const float* __restrict__ b_ih, const float* __restrict__ b_hh,
                     const float* __restrict__ W_dec, const float* __restrict__ b_dec,
                     float* __restrict__ out)
{
    extern __shared__ char smb[];
    bf16* sW16 = (bf16*)(smb + OFF_W);            // stride 392 bf16
    const u32* w32 = (const u32*)(smb + OFF_W);   // stride 196 u32
    bf16* sA16 = (bf16*)(smb + OFF_A);
    u32*  aU   = (u32*)(smb + OFF_A);
    float* scr = (float*)(smb + OFF_SCR);
    float* gb  = (float*)(smb + OFF_G);
    float* sb  = (float*)(smb + OFF_SB);
    float* sWd = (float*)(smb + OFF_WD);

    const int tid  = threadIdx.x;
    const int cb   = blockIdx.x & 15;
    const int cu   = blockIdx.x >> 4;
    const int B0   = cb * 16;
    const int U0   = cu * 16;

    const int lane = tid & 31;
    const int wid  = tid >> 5;
    const int nq   = wid & 3;             // 16-col n-quarter
    const int kq   = wid >> 2;            // k16-tile parity
    const int lg   = lane >> 2;
    const int lt   = lane & 3;

    // ---- stage W (bf16), zero h-region, biases, W_dec, x(0)
    for (int idx = tid; idx < 48 * 384; idx += NTHREADS) {
        int gr = idx / 384, k = idx - gr * 384;
        int g = gr >> 4, uu = gr & 15, grow = g * HID + U0 + uu;
        float v = (k < HID) ? W_hh[grow * HID + k] : W_ih[grow * IN_DIM + (k - HID)];
        sW16[gr * 392 + k] = __float2bfloat16_rn(v);
    }
    for (int i = tid; i < 2048; i += NTHREADS) {          // h(0) = 0 (16 x 128 u32)
        int r = i >> 7, c0 = i & 127;
        aU[r * 196 + c0] = 0u;
    }
    if (tid < 16) {
        sb[tid]      = b_ih[U0 + tid] + b_hh[U0 + tid];              // r
        sb[16 + tid] = b_ih[HID + U0 + tid] + b_hh[HID + U0 + tid];  // z
        sb[32 + tid] = b_hh[2 * HID + U0 + tid];                     // n (h side)
        sb[48 + tid] = b_ih[2 * HID + U0 + tid];                     // n (x side)
    }
    sWd[tid] = W_dec[tid];
    {
        int row = tid >> 4;
        const uint4* src = (const uint4*)(g_xb + (size_t)(B0 + row) * IN_DIM);
        ((uint4*)(smb + OFF_A + row * 784 + 512))[tid & 15] = __ldg(src + (tid & 15));
    }
    __syncthreads();

    // ---- hoist B fragments (weights) into registers for all steps
    u32 Bh[2][8][2], Bx[2][4][2];
    #pragma unroll
    for (int ntl = 0; ntl < 2; ++ntl) {
        int col = 8 * (2 * nq + ntl) + lg;
        int prow = (col < 48) ? col : col - 16;           // ni cols -> rows 32-47
        const u32* wp = w32 + prow * 196 + lt;
        #pragma unroll
        for (int j = 0; j < 8; ++j) {
            int kt = 2 * j + kq;
            Bh[ntl][j][0] = wp[8 * kt];
            Bh[ntl][j][1] = wp[8 * kt + 4];
        }
        #pragma unroll
        for (int j = 0; j < 4; ++j) {
            int kt = 16 + 2 * j + kq;
            Bx[ntl][j][0] = wp[8 * kt];
            Bx[ntl][j][1] = wp[8 * kt + 4];
        }
    }

    const float bdec = b_dec[0];
    float loss_local = 0.0f;
    int p = 0;
    unsigned* cnt = &g_arr[cb * 32];

    const u32* aP = aU + lg * 196 + lt;                   // A-frag base
    const int erow = tid >> 4, eu = tid & 15;
    float hp = 0.0f;                                      // fp32 state in register
    float* scrW = scr + nq * 288 + lg * 18 + 2 * lt;
    float* gbW  = gb + lg * 68 + nq * 16 + 2 * lt;

    for (int t = 0; t < STEPS; ++t) {
        float c[2][4] = {{0.f,0.f,0.f,0.f},{0.f,0.f,0.f,0.f}};

        // ---- x-part MMA (k16 tiles 16..23, parity kq) BEFORE the wait
        if (nq != 2) {
            #pragma unroll
            for (int j = 0; j < 4; ++j) {
                int kt = 16 + 2 * j + kq;
                u32 a0 = aP[8 * kt], a1 = aP[8 * kt + 1568];
                u32 a2 = aP[8 * kt + 4], a3 = aP[8 * kt + 4 + 1568];
                mma16(c[0], a0, a1, a2, a3, Bx[0][j][0], Bx[0][j][1]);
                mma16(c[1], a0, a1, a2, a3, Bx[1][j][0], Bx[1][j][1]);
            }
        }

        // ---- per-warp wait for h(t)
        if (t > 0) {
            if (lane == 0) {
                unsigned target = (unsigned)t * 128u;
                while (ld_acq(cnt) < target) __nanosleep(20);
            }
            __syncwarp();
        }

        // ---- stage h(t): each warp its 2 rows (bf16 copy)
        {
            int row = 2 * wid + (lane >> 4);
            const uint4* src = (const uint4*)(g_hb[p] + (B0 + row) * HID);
            uint4* dst = (uint4*)(smb + OFF_A + row * 784);
            int c0 = lane & 15;
            dst[c0]      = __ldcg(src + c0);
            dst[c0 + 16] = __ldcg(src + c0 + 16);
        }
        __syncthreads();                                  // sync1

        // ---- loss for h(t) on warp 7 (ni/kq1: no h-MMA)
        if (wid == 7 && t > 0) {
            const bf16* hr = sA16 + cu * 392;
            float s = 0.0f;
            #pragma unroll
            for (int q = 0; q < 8; ++q) {
                int k = lane + 32 * q;
                s += __bfloat162float(hr[k]) * sWd[k];
            }
            #pragma unroll
            for (int sft = 16; sft > 0; sft >>= 1)
                s += __shfl_down_sync(0xffffffffu, s, sft);
            if (lane == 0) {
                float l = s + bdec;
                float g = gt[t * BATCH + B0 + cu];
                loss_local += fmaxf(l, 0.0f) + log1pf(__expf(-fabsf(l))) - g * l;
            }
        }

        // ---- h-part MMA (k16 tiles 0..15, parity kq)
        if (nq != 3) {
            #pragma unroll
            for (int j = 0; j < 8; ++j) {
                int kt = 2 * j + kq;
                u32 a0 = aP[8 * kt], a1 = aP[8 * kt + 1568];
                u32 a2 = aP[8 * kt + 4], a3 = aP[8 * kt + 4 + 1568];
                mma16(c[0], a0, a1, a2, a3, Bh[0][j][0], Bh[0][j][1]);
                mma16(c[1], a0, a1, a2, a3, Bh[1][j][0], Bh[1][j][1]);
            }
        }

        // ---- kq1 stores partials; restage x(t+1)
        if (kq == 1) {
            #pragma unroll
            for (int ntl = 0; ntl < 2; ++ntl) {
                *(float2*)(scrW + ntl * 8)          = make_float2(c[ntl][0], c[ntl][1]);
                *(float2*)(scrW + ntl * 8 + 8 * 18) = make_float2(c[ntl][2], c[ntl][3]);
            }
        }
        if (t + 1 < STEPS) {
            int row = tid >> 4;
            const uint4* src = (const uint4*)(g_xb + ((size_t)(t + 1) * BATCH + B0 + row) * IN_DIM);
            ((uint4*)(smb + OFF_A + row * 784 + 512))[tid & 15] = __ldg(src + (tid & 15));
        }
        __syncthreads();                                  // sync2

        // ---- kq0 adds partials, writes gate buffer
        if (kq == 0) {
            #pragma unroll
            for (int ntl = 0; ntl < 2; ++ntl) {
                float2 u0 = *(float2*)(scrW + ntl * 8);
                float2 u1 = *(float2*)(scrW + ntl * 8 + 8 * 18);
                *(float2*)(gbW + ntl * 8)          = make_float2(c[ntl][0] + u0.x, c[ntl][1] + u0.y);
                *(float2*)(gbW + ntl * 8 + 8 * 68) = make_float2(c[ntl][2] + u1.x, c[ntl][3] + u1.y);
            }
        }
        __syncthreads();                                  // sync3

        // ---- epilogue: one h element per thread; per-warp release
        {
            float rr = gb[erow * 68 + eu];
            float zz = gb[erow * 68 + 16 + eu];
            float hh = gb[erow * 68 + 32 + eu];
            float ii = gb[erow * 68 + 48 + eu];
            float rv = sigap(rr + sb[eu]);
            float zv = sigap(zz + sb[16 + eu]);
            float pre = ii + sb[48 + eu] + rv * (hh + sb[32 + eu]);
            float nv = tanhap(pre);
            float hn = nv + zv * (hp - nv);
            hp = hn;                                              // carry fp32
            g_hb[p ^ 1][(B0 + erow) * HID + U0 + eu] = __float2bfloat16_rn(hn);
        }
        __syncwarp();
        if (lane == 0) red_release(cnt);
        p ^= 1;
    }

    // ---- final loss: h(511), gt[511]
    if (tid == 0) {
        while (ld_acq(cnt) < (unsigned)STEPS * 128u) __nanosleep(20);
    }
    __syncthreads();
    if (tid < 32) {
        const bf16* hr = g_hb[p] + (B0 + cu) * HID;
        float s = 0.0f;
        #pragma unroll
        for (int q = 0; q < 8; ++q) {
            int k = lane + 32 * q;
            s += __bfloat162float(hr[k]) * sWd[k];
        }
        #pragma unroll
        for (int sft = 16; sft > 0; sft >>= 1)
            s += __shfl_down_sync(0xffffffffu, s, sft);
        if (lane == 0) {
            float l = s + bdec;
            float g = gt[(size_t)STEPS * BATCH + B0 + cu];
            loss_local += fmaxf(l, 0.0f) + log1pf(__expf(-fabsf(l))) - g * l;
        }
    }
    if (tid == 0 || (wid == 7 && lane == 0)) atomicAdd(out, loss_local);
}

extern "C" void kernel_launch(void* const* d_in, const int* in_sizes, int n_in,
                              void* d_out, int out_size) {
    const float* x     = (const float*)d_in[0];
    const float* gt    = (const float*)d_in[1];
    const float* W_ih  = (const float*)d_in[2];
    const float* W_hh  = (const float*)d_in[3];
    const float* b_ih  = (const float*)d_in[4];
    const float* b_hh  = (const float*)d_in[5];
    const float* W_dec = (const float*)d_in[6];
    const float* b_dec = (const float*)d_in[7];
    float* out = (float*)d_out;

    cudaFuncSetAttribute(gru_main_kernel,
                         cudaFuncAttributeMaxDynamicSharedMemorySize, SMEM_BYTES);

    gru_init_kernel<<<1024, 256>>>(out, x);
    gru_main_kernel<<<NCTA, NTHREADS, SMEM_BYTES>>>(
        x, gt, W_ih, W_hh, b_ih, b_hh, W_dec, b_dec, out);
}

// round 15
// speedup vs baseline: 1.3584x; 1.0151x over previous
#include <cuda_runtime.h>
#include <cuda_bf16.h>

// ---------------------------------------------------------------------------
// GRU (511 steps) + BCE via mma.sync m16n8k16 bf16 (fp32 accum). Persistent,
// 256 CTAs (16 batch x 16 unit groups), 2 CTAs/SM.
// CTA GEMM/step: [16 rows] x [64 cols: r16|z16|nh16|ni16] x K=384 (24 k16).
// R15: warp = one 8-col n-tile over FULL K with B (weights) register-
// resident; two parity accumulator chains per warp -> NO cross-warp
// K-reduction; 2 syncthreads/step. Post-wait MMA load balanced (16/16/16/
// 16/16/16/0/0). h exchanged bf16; fp32 state in register (hp).
// ---------------------------------------------------------------------------

#define BATCH 256
#define IN_DIM 128
#define HID 256
#define STEPS 511
#define NCTA 256
#define NTHREADS 256

// byte offsets; W/A rows: u32-stride 196 (392 bf16 = 784B)
#define OFF_W   0                         // 48 x 784
#define OFF_A   37632                     // 16 x 784
#define OFF_G   50176                     // 16 x 68 floats
#define OFF_SB  54528                     // 64 floats
#define OFF_WD  54784                     // 256 floats
#define SMEM_BYTES 55808

typedef unsigned int u32;
typedef __nv_bfloat16 bf16;

__device__ bf16 g_hb[2][BATCH * HID];
__device__ bf16 g_xb[(size_t)STEPS * BATCH * IN_DIM];
__device__ unsigned g_arr[16 * 32];

__global__ void gru_init_kernel(float* out, const float* __restrict__ x) {
    int i = blockIdx.x * blockDim.x + threadIdx.x;
    int stride = gridDim.x * blockDim.x;
    if (i == 0) out[0] = 0.0f;
    if (i < 512) g_arr[i] = 0u;
    u32* h0 = (u32*)g_hb[0];
    for (int j = i; j < BATCH * HID / 2; j += stride) h0[j] = 0u;
    const float2* x2 = (const float2*)x;
    u32* xb = (u32*)g_xb;
    int n2 = (int)((size_t)STEPS * BATCH * IN_DIM / 2);
    for (int j = i; j < n2; j += stride) {
        float2 v = x2[j];
        u32 r;
        asm("cvt.rn.bf16x2.f32 %0, %1, %2;" : "=r"(r) : "f"(v.y), "f"(v.x));
        xb[j] = r;
    }
}

__device__ __forceinline__ void mma16(float* c, u32 a0, u32 a1, u32 a2, u32 a3,
                                      u32 b0, u32 b1) {
    asm volatile(
        "mma.sync.aligned.m16n8k16.row.col.f32.bf16.bf16.f32 "
        "{%0,%1,%2,%3}, {%4,%5,%6,%7}, {%8,%9}, {%0,%1,%2,%3};"
        : "+f"(c[0]), "+f"(c[1]), "+f"(c[2]), "+f"(c[3])
        : "r"(a0), "r"(a1), "r"(a2), "r"(a3), "r"(b0), "r"(b1));
}
__device__ __forceinline__ float tanhap(float v) {
    float r;
    asm("tanh.approx.f32 %0, %1;" : "=f"(r) : "f"(v));
    return r;
}
__device__ __forceinline__ float sigap(float v) {
    return 0.5f * tanhap(0.5f * v) + 0.5f;
}
__device__ __forceinline__ unsigned ld_acq(const unsigned* p) {
    unsigned v;
    asm volatile("ld.acquire.gpu.global.u32 %0, [%1];" : "=r"(v) : "l"(p) : "memory");
    return v;
}
__device__ __forceinline__ void red_release(unsigned* p) {
    asm volatile("red.release.gpu.global.add.u32 [%0], %1;" :: "l"(p), "r"(1u) : "memory");
}

__global__ __launch_bounds__(NTHREADS, 2)
void gru_main_kernel(const float* __restrict__ x, const float* __restrict__ gt,
                     const float* __restrict__ W_ih, const float* __restrict__ W_hh,
                     const float* __restrict__ b_ih, const float* __restrict__ b_hh,
                     const float* __restrict__ W_dec, const float* __restrict__ b_dec,
                     float* __restrict__ out)
{
    extern __shared__ char smb[];
    bf16* sW16 = (bf16*)(smb + OFF_W);
    const u32* w32 = (const u32*)(smb + OFF_W);
    bf16* sA16 = (bf16*)(smb + OFF_A);
    u32*  aU   = (u32*)(smb + OFF_A);
    float* gb  = (float*)(smb + OFF_G);
    float* sb  = (float*)(smb + OFF_SB);
    float* sWd = (float*)(smb + OFF_WD);

    const int tid  = threadIdx.x;
    const int cb   = blockIdx.x & 15;
    const int cu   = blockIdx.x >> 4;
    const int B0   = cb * 16;
    const int U0   = cu * 16;

    const int lane = tid & 31;
    const int wid  = tid >> 5;            // n-tile: cols 8*wid..8*wid+7
    const int lg   = lane >> 2;
    const int lt   = lane & 3;
    const bool hact = (wid < 6);          // r,z,nh tiles use h k-range
    const bool xact = (wid < 4) || (wid >= 6);   // r,z,ni use x k-range

    // ---- stage W (bf16), zero h-region, biases, W_dec, x(0)
    for (int idx = tid; idx < 48 * 384; idx += NTHREADS) {
        int gr = idx / 384, k = idx - gr * 384;
        int g = gr >> 4, uu = gr & 15, grow = g * HID + U0 + uu;
        float v = (k < HID) ? W_hh[grow * HID + k] : W_ih[grow * IN_DIM + (k - HID)];
        sW16[gr * 392 + k] = __float2bfloat16_rn(v);
    }
    for (int i = tid; i < 2048; i += NTHREADS) {
        int r = i >> 7, c0 = i & 127;
        aU[r * 196 + c0] = 0u;                          // h(0) = 0
    }
    if (tid < 16) {
        sb[tid]      = b_ih[U0 + tid] + b_hh[U0 + tid];              // r
        sb[16 + tid] = b_ih[HID + U0 + tid] + b_hh[HID + U0 + tid];  // z
        sb[32 + tid] = b_hh[2 * HID + U0 + tid];                     // n (h side)
        sb[48 + tid] = b_ih[2 * HID + U0 + tid];                     // n (x side)
    }
    sWd[tid] = W_dec[tid];
    {
        int row = tid >> 4;
        const uint4* src = (const uint4*)(g_xb + (size_t)(B0 + row) * IN_DIM);
        ((uint4*)(smb + OFF_A + row * 784 + 512))[tid & 15] = __ldg(src + (tid & 15));
    }
    __syncthreads();

    // ---- hoist B fragments for ALL 24 k-tiles into registers
    // (nh cols 32-47 and ni cols 48-63 share physical rows 32-47)
    u32 B[24][2];
    {
        int col = 8 * wid + lg;
        int prow = (col < 48) ? col : col - 16;
        const u32* wp = w32 + prow * 196 + lt;
        #pragma unroll
        for (int kt = 0; kt < 24; ++kt) {
            B[kt][0] = wp[8 * kt];
            B[kt][1] = wp[8 * kt + 4];
        }
    }

    const float bdec = b_dec[0];
    float loss_local = 0.0f;
    int p = 0;
    unsigned* cnt = &g_arr[cb * 32];

    const u32* aP = aU + lg * 196 + lt;
    const int erow = tid >> 4, eu = tid & 15;
    float hp = 0.0f;                                   // fp32 state in register
    float* gbW = gb + lg * 68 + 8 * wid + 2 * lt;

    for (int t = 0; t < STEPS; ++t) {
        float c0[4] = {0.f,0.f,0.f,0.f};               // even-parity chain
        float c1[4] = {0.f,0.f,0.f,0.f};               // odd-parity chain

        // ---- x-part MMA (k-tiles 16..23) BEFORE the wait
        if (xact) {
            #pragma unroll
            for (int j = 0; j < 4; ++j) {
                int k0 = 16 + 2 * j, k1 = 17 + 2 * j;
                mma16(c0, aP[8 * k0], aP[8 * k0 + 1568], aP[8 * k0 + 4],
                          aP[8 * k0 + 4 + 1568], B[k0][0], B[k0][1]);
                mma16(c1, aP[8 * k1], aP[8 * k1 + 1568], aP[8 * k1 + 4],
                          aP[8 * k1 + 4 + 1568], B[k1][0], B[k1][1]);
            }
        }

        // ---- per-warp wait for h(t)
        if (t > 0) {
            if (lane == 0) {
                unsigned target = (unsigned)t * 128u;
                while (ld_acq(cnt) < target) __nanosleep(20);
            }
            __syncwarp();
        }

        // ---- stage h(t): each warp its 2 rows (bf16 copy)
        {
            int row = 2 * wid + (lane >> 4);
            const uint4* src = (const uint4*)(g_hb[p] + (B0 + row) * HID);
            uint4* dst = (uint4*)(smb + OFF_A + row * 784);
            int cc = lane & 15;
            dst[cc]      = __ldcg(src + cc);
            dst[cc + 16] = __ldcg(src + cc + 16);
        }
        __syncthreads();                               // sync1 (also: x(t) reads done)

        // ---- loss for h(t) on warp 7 (x-only warp, free post-wait)
        if (wid == 7 && t > 0) {
            const bf16* hr = sA16 + cu * 392;
            float s = 0.0f;
            #pragma unroll
            for (int q = 0; q < 8; ++q) {
                int k = lane + 32 * q;
                s += __bfloat162float(hr[k]) * sWd[k];
            }
            #pragma unroll
            for (int sft = 16; sft > 0; sft >>= 1)
                s += __shfl_down_sync(0xffffffffu, s, sft);
            if (lane == 0) {
                float l = s + bdec;
                float g = gt[t * BATCH + B0 + cu];
                loss_local += fmaxf(l, 0.0f) + log1pf(__expf(-fabsf(l))) - g * l;
            }
        }

        // ---- h-part MMA (k-tiles 0..15), two 8-deep chains
        if (hact) {
            #pragma unroll
            for (int j = 0; j < 8; ++j) {
                int k0 = 2 * j, k1 = 2 * j + 1;
                mma16(c0, aP[8 * k0], aP[8 * k0 + 1568], aP[8 * k0 + 4],
                          aP[8 * k0 + 4 + 1568], B[k0][0], B[k0][1]);
                mma16(c1, aP[8 * k1], aP[8 * k1 + 1568], aP[8 * k1 + 4],
                          aP[8 * k1 + 4 + 1568], B[k1][0], B[k1][1]);
            }
        }

        // ---- combine chains, write finished gate columns (no K-reduction)
        *(float2*)(gbW)          = make_float2(c0[0] + c1[0], c0[1] + c1[1]);
        *(float2*)(gbW + 8 * 68) = make_float2(c0[2] + c1[2], c0[3] + c1[3]);

        // ---- restage x(t+1) (safe: sync1 proved all x(t) reads complete)
        if (t + 1 < STEPS) {
            int row = tid >> 4;
            const uint4* src = (const uint4*)(g_xb + ((size_t)(t + 1) * BATCH + B0 + row) * IN_DIM);
            ((uint4*)(smb + OFF_A + row * 784 + 512))[tid & 15] = __ldg(src + (tid & 15));
        }
        __syncthreads();                               // sync2 (gb + restage done)

        // ---- epilogue: one h element per thread; per-warp release
        {
            float rr = gb[erow * 68 + eu];
            float zz = gb[erow * 68 + 16 + eu];
            float hh = gb[erow * 68 + 32 + eu];
            float ii = gb[erow * 68 + 48 + eu];
            float rv = sigap(rr + sb[eu]);
            float zv = sigap(zz + sb[16 + eu]);
            float pre = ii + sb[48 + eu] + rv * (hh + sb[32 + eu]);
            float nv = tanhap(pre);
            float hn = nv + zv * (hp - nv);
            hp = hn;
            g_hb[p ^ 1][(B0 + erow) * HID + U0 + eu] = __float2bfloat16_rn(hn);
        }
        __syncwarp();
        if (lane == 0) red_release(cnt);
        p ^= 1;
    }

    // ---- final loss: h(511), gt[511]
    if (tid == 0) {
        while (ld_acq(cnt) < (unsigned)STEPS * 128u) __nanosleep(20);
    }
    __syncthreads();
    if (tid < 32) {
        const bf16* hr = g_hb[p] + (B0 + cu) * HID;
        float s = 0.0f;
        #pragma unroll
        for (int q = 0; q < 8; ++q) {
            int k = lane + 32 * q;
            s += __bfloat162float(hr[k]) * sWd[k];
        }
        #pragma unroll
        for (int sft = 16; sft > 0; sft >>= 1)
            s += __shfl_down_sync(0xffffffffu, s, sft);
        if (lane == 0) {
            float l = s + bdec;
            float g = gt[(size_t)STEPS * BATCH + B0 + cu];
            loss_local += fmaxf(l, 0.0f) + log1pf(__expf(-fabsf(l))) - g * l;
        }
    }
    if (tid == 0 || (wid == 7 && lane == 0)) atomicAdd(out, loss_local);
}

extern "C" void kernel_launch(void* const* d_in, const int* in_sizes, int n_in,
                              void* d_out, int out_size) {
    const float* x     = (const float*)d_in[0];
    const float* gt    = (const float*)d_in[1];
    const float* W_ih  = (const float*)d_in[2];
    const float* W_hh  = (const float*)d_in[3];
    const float* b_ih  = (const float*)d_in[4];
    const float* b_hh  = (const float*)d_in[5];
    const float* W_dec = (const float*)d_in[6];
    const float* b_dec = (const float*)d_in[7];
    float* out = (float*)d_out;

    cudaFuncSetAttribute(gru_main_kernel,
                         cudaFuncAttributeMaxDynamicSharedMemorySize, SMEM_BYTES);

    gru_init_kernel<<<1024, 256>>>(out, x);
    gru_main_kernel<<<NCTA, NTHREADS, SMEM_BYTES>>>(
        x, gt, W_ih, W_hh, b_ih, b_hh, W_dec, b_dec, out);
}

// round 16
// speedup vs baseline: 1.5584x; 1.1472x over previous
#include <cuda_runtime.h>
#include <cuda_bf16.h>

// ---------------------------------------------------------------------------
// GRU (511 steps) + BCE via mma.sync m16n8k16 bf16. Persistent, 256 CTAs
// (16 batch x 16 unit groups), 2 CTAs/SM.
// R16: tile-major h exchange (g_ht[cb][cu] = contiguous 512B 16x16 tile),
// per-producer-CTA counters; consumer warp w waits ONLY on its two source
// CTAs (2w, 2w+1) and stages their 32 columns. No global coupling.
// Warp = one 8-col n-tile over FULL K, B register-resident, 2 parity
// accumulator chains, 2 syncthreads/step. fp32 state in register (hp).
// ---------------------------------------------------------------------------

#define BATCH 256
#define IN_DIM 128
#define HID 256
#define STEPS 511
#define NCTA 256
#define NTHREADS 256

// byte offsets; W/A rows: u32-stride 196 (392 bf16 = 784B)
#define OFF_W   0                         // 48 x 784
#define OFF_A   37632                     // 16 x 784
#define OFF_G   50176                     // 16 x 68 floats
#define OFF_SB  54528                     // 64 floats
#define OFF_WD  54784                     // 256 floats
#define SMEM_BYTES 55808

typedef unsigned int u32;
typedef __nv_bfloat16 bf16;

__device__ bf16 g_ht[2][256 * 256];                  // [cb*16+cu][row][16] tiles
__device__ bf16 g_xb[(size_t)STEPS * BATCH * IN_DIM];
__device__ unsigned g_cnt[256 * 32];                 // per-CTA counters, 128B apart

__global__ void gru_init_kernel(float* out, const float* __restrict__ x) {
    int i = blockIdx.x * blockDim.x + threadIdx.x;
    int stride = gridDim.x * blockDim.x;
    if (i == 0) out[0] = 0.0f;
    for (int j = i; j < 256 * 32; j += stride) g_cnt[j] = 0u;
    u32* h0 = (u32*)g_ht[0];
    for (int j = i; j < 256 * 256 / 2; j += stride) h0[j] = 0u;
    const float2* x2 = (const float2*)x;
    u32* xb = (u32*)g_xb;
    int n2 = (int)((size_t)STEPS * BATCH * IN_DIM / 2);
    for (int j = i; j < n2; j += stride) {
        float2 v = x2[j];
        u32 r;
        asm("cvt.rn.bf16x2.f32 %0, %1, %2;" : "=r"(r) : "f"(v.y), "f"(v.x));
        xb[j] = r;
    }
}

__device__ __forceinline__ void mma16(float* c, u32 a0, u32 a1, u32 a2, u32 a3,
                                      u32 b0, u32 b1) {
    asm volatile(
        "mma.sync.aligned.m16n8k16.row.col.f32.bf16.bf16.f32 "
        "{%0,%1,%2,%3}, {%4,%5,%6,%7}, {%8,%9}, {%0,%1,%2,%3};"
        : "+f"(c[0]), "+f"(c[1]), "+f"(c[2]), "+f"(c[3])
        : "r"(a0), "r"(a1), "r"(a2), "r"(a3), "r"(b0), "r"(b1));
}
__device__ __forceinline__ float tanhap(float v) {
    float r;
    asm("tanh.approx.f32 %0, %1;" : "=f"(r) : "f"(v));
    return r;
}
__device__ __forceinline__ float sigap(float v) {
    return 0.5f * tanhap(0.5f * v) + 0.5f;
}
__device__ __forceinline__ unsigned ld_acq(const unsigned* p) {
    unsigned v;
    asm volatile("ld.acquire.gpu.global.u32 %0, [%1];" : "=r"(v) : "l"(p) : "memory");
    return v;
}
__device__ __forceinline__ void red_release(unsigned* p) {
    asm volatile("red.release.gpu.global.add.u32 [%0], %1;" :: "l"(p), "r"(1u) : "memory");
}

__global__ __launch_bounds__(NTHREADS, 2)
void gru_main_kernel(const float* __restrict__ x, const float* __restrict__ gt,
                     const float* __restrict__ W_ih, const float* __restrict__ W_hh,
                     const float* __restrict__ b_ih, const float* __restrict__ b_hh,
                     const float* __restrict__ W_dec, const float* __restrict__ b_dec,
                     float* __restrict__ out)
{
    extern __shared__ char smb[];
    bf16* sW16 = (bf16*)(smb + OFF_W);
    const u32* w32 = (const u32*)(smb + OFF_W);
    bf16* sA16 = (bf16*)(smb + OFF_A);
    u32*  aU   = (u32*)(smb + OFF_A);
    float* gb  = (float*)(smb + OFF_G);
    float* sb  = (float*)(smb + OFF_SB);
    float* sWd = (float*)(smb + OFF_WD);

    const int tid  = threadIdx.x;
    const int cb   = blockIdx.x & 15;
    const int cu   = blockIdx.x >> 4;
    const int B0   = cb * 16;
    const int U0   = cu * 16;

    const int lane = tid & 31;
    const int wid  = tid >> 5;            // n-tile: cols 8*wid..8*wid+7
    const int lg   = lane >> 2;
    const int lt   = lane & 3;
    const bool hact = (wid < 6);
    const bool xact = (wid < 4) || (wid >= 6);

    // ---- stage W (bf16), zero h-region, biases, W_dec, x(0)
    for (int idx = tid; idx < 48 * 384; idx += NTHREADS) {
        int gr = idx / 384, k = idx - gr * 384;
        int g = gr >> 4, uu = gr & 15, grow = g * HID + U0 + uu;
        float v = (k < HID) ? W_hh[grow * HID + k] : W_ih[grow * IN_DIM + (k - HID)];
        sW16[gr * 392 + k] = __float2bfloat16_rn(v);
    }
    for (int i = tid; i < 2048; i += NTHREADS) {
        int r = i >> 7, c0 = i & 127;
        aU[r * 196 + c0] = 0u;                          // h(0) = 0
    }
    if (tid < 16) {
        sb[tid]      = b_ih[U0 + tid] + b_hh[U0 + tid];              // r
        sb[16 + tid] = b_ih[HID + U0 + tid] + b_hh[HID + U0 + tid];  // z
        sb[32 + tid] = b_hh[2 * HID + U0 + tid];                     // n (h side)
        sb[48 + tid] = b_ih[2 * HID + U0 + tid];                     // n (x side)
    }
    sWd[tid] = W_dec[tid];
    {
        int row = tid >> 4;
        const uint4* src = (const uint4*)(g_xb + (size_t)(B0 + row) * IN_DIM);
        ((uint4*)(smb + OFF_A + row * 784 + 512))[tid & 15] = __ldg(src + (tid & 15));
    }
    __syncthreads();

    // ---- hoist B fragments for ALL 24 k-tiles into registers
    u32 B[24][2];
    {
        int col = 8 * wid + lg;
        int prow = (col < 48) ? col : col - 16;
        const u32* wp = w32 + prow * 196 + lt;
        #pragma unroll
        for (int kt = 0; kt < 24; ++kt) {
            B[kt][0] = wp[8 * kt];
            B[kt][1] = wp[8 * kt + 4];
        }
    }

    const float bdec = b_dec[0];
    float loss_local = 0.0f;
    int p = 0;

    // sources for this consumer warp: unit-CTAs 2w, 2w+1 of the same cb
    const unsigned* csrc0 = &g_cnt[(cb * 16 + 2 * wid) * 32];
    const unsigned* csrc1 = &g_cnt[(cb * 16 + 2 * wid + 1) * 32];
    unsigned* cown = &g_cnt[(cb * 16 + cu) * 32];

    const u32* aP = aU + lg * 196 + lt;
    const int erow = tid >> 4, eu = tid & 15;
    float hp = 0.0f;
    float* gbW = gb + lg * 68 + 8 * wid + 2 * lt;
    // staging geometry: lane -> (row = lane>>1, colhalf = lane&1)
    const int srow = lane >> 1, sch = lane & 1;

    for (int t = 0; t < STEPS; ++t) {
        float c0[4] = {0.f,0.f,0.f,0.f};
        float c1[4] = {0.f,0.f,0.f,0.f};

        // ---- x-part MMA (k-tiles 16..23) BEFORE the wait
        if (xact) {
            #pragma unroll
            for (int j = 0; j < 4; ++j) {
                int k0 = 16 + 2 * j, k1 = 17 + 2 * j;
                mma16(c0, aP[8 * k0], aP[8 * k0 + 1568], aP[8 * k0 + 4],
                          aP[8 * k0 + 4 + 1568], B[k0][0], B[k0][1]);
                mma16(c1, aP[8 * k1], aP[8 * k1 + 1568], aP[8 * k1 + 4],
                          aP[8 * k1 + 4 + 1568], B[k1][0], B[k1][1]);
            }
        }

        // ---- wait ONLY on this warp's two source CTAs (lanes 0/1 in parallel)
        if (t > 0) {
            if (lane < 2) {
                const unsigned* cp = lane ? csrc1 : csrc0;
                unsigned target = (unsigned)t * 8u;
                while (ld_acq(cp) < target) { }
            }
            __syncwarp();
        }

        // ---- stage the two source tiles (each 512B contiguous, coalesced)
        {
            const uint4* t0 = (const uint4*)(g_ht[p] + (cb * 16 + 2 * wid) * 256);
            const uint4* t1 = (const uint4*)(g_ht[p] + (cb * 16 + 2 * wid + 1) * 256);
            uint4 v0 = __ldcg(t0 + lane);
            uint4 v1 = __ldcg(t1 + lane);
            // sA dest: row srow, cols (src*16 + 8*sch)
            *(uint4*)(smb + OFF_A + srow * 784 + (2 * wid) * 32 + 16 * sch)      = v0;
            *(uint4*)(smb + OFF_A + srow * 784 + (2 * wid + 1) * 32 + 16 * sch)  = v1;
        }
        __syncthreads();                               // sync1

        // ---- loss for h(t) on warp 7 (x-only warp)
        if (wid == 7 && t > 0) {
            const bf16* hr = sA16 + cu * 392;
            float s = 0.0f;
            #pragma unroll
            for (int q = 0; q < 8; ++q) {
                int k = lane + 32 * q;
                s += __bfloat162float(hr[k]) * sWd[k];
            }
            #pragma unroll
            for (int sft = 16; sft > 0; sft >>= 1)
                s += __shfl_down_sync(0xffffffffu, s, sft);
            if (lane == 0) {
                float l = s + bdec;
                float g = gt[t * BATCH + B0 + cu];
                loss_local += fmaxf(l, 0.0f) + log1pf(__expf(-fabsf(l))) - g * l;
            }
        }

        // ---- h-part MMA (k-tiles 0..15), two 8-deep chains
        if (hact) {
            #pragma unroll
            for (int j = 0; j < 8; ++j) {
                int k0 = 2 * j, k1 = 2 * j + 1;
                mma16(c0, aP[8 * k0], aP[8 * k0 + 1568], aP[8 * k0 + 4],
                          aP[8 * k0 + 4 + 1568], B[k0][0], B[k0][1]);
                mma16(c1, aP[8 * k1], aP[8 * k1 + 1568], aP[8 * k1 + 4],
                          aP[8 * k1 + 4 + 1568], B[k1][0], B[k1][1]);
            }
        }

        // ---- combine chains, write gate columns
        *(float2*)(gbW)          = make_float2(c0[0] + c1[0], c0[1] + c1[1]);
        *(float2*)(gbW + 8 * 68) = make_float2(c0[2] + c1[2], c0[3] + c1[3]);

        // ---- restage x(t+1)
        if (t + 1 < STEPS) {
            int row = tid >> 4;
            const uint4* src = (const uint4*)(g_xb + ((size_t)(t + 1) * BATCH + B0 + row) * IN_DIM);
            ((uint4*)(smb + OFF_A + row * 784 + 512))[tid & 15] = __ldg(src + (tid & 15));
        }
        __syncthreads();                               // sync2

        // ---- epilogue: one h element per thread; per-warp release of OWN CTA
        {
            float rr = gb[erow * 68 + eu];
            float zz = gb[erow * 68 + 16 + eu];
            float hh = gb[erow * 68 + 32 + eu];
            float ii = gb[erow * 68 + 48 + eu];
            float rv = sigap(rr + sb[eu]);
            float zv = sigap(zz + sb[16 + eu]);
            float pre = ii + sb[48 + eu] + rv * (hh + sb[32 + eu]);
            float nv = tanhap(pre);
            float hn = nv + zv * (hp - nv);
            hp = hn;
            // tile-major store: contiguous within the CTA's 512B tile
            g_ht[p ^ 1][(cb * 16 + cu) * 256 + erow * 16 + eu] = __float2bfloat16_rn(hn);
        }
        __syncwarp();
        if (lane == 0) red_release(cown);
        p ^= 1;
    }

    // ---- final loss: h(511) from own-group tiles, gt[511]
    if (tid < 32) {
        if (lane < 16) {
            const unsigned* cp = &g_cnt[(cb * 16 + lane) * 32];
            while (ld_acq(cp) < (unsigned)STEPS * 8u) { }
        }
        __syncwarp();
        float s = 0.0f;
        #pragma unroll
        for (int q = 0; q < 8; ++q) {
            int k = lane + 32 * q;
            s += __bfloat162float(g_ht[p][(cb * 16 + (k >> 4)) * 256 + cu * 16 + (k & 15)]) * sWd[k];
        }
        #pragma unroll
        for (int sft = 16; sft > 0; sft >>= 1)
            s += __shfl_down_sync(0xffffffffu, s, sft);
        if (lane == 0) {
            float l = s + bdec;
            float g = gt[(size_t)STEPS * BATCH + B0 + cu];
            loss_local += fmaxf(l, 0.0f) + log1pf(__expf(-fabsf(l))) - g * l;
        }
    }
    if (tid == 0 || (wid == 7 && lane == 0)) atomicAdd(out, loss_local);
}

extern "C" void kernel_launch(void* const* d_in, const int* in_sizes, int n_in,
                              void* d_out, int out_size) {
    const float* x     = (const float*)d_in[0];
    const float* gt    = (const float*)d_in[1];
    const float* W_ih  = (const float*)d_in[2];
    const float* W_hh  = (const float*)d_in[3];
    const float* b_ih  = (const float*)d_in[4];
    const float* b_hh  = (const float*)d_in[5];
    const float* W_dec = (const float*)d_in[6];
    const float* b_dec = (const float*)d_in[7];
    float* out = (float*)d_out;

    cudaFuncSetAttribute(gru_main_kernel,
                         cudaFuncAttributeMaxDynamicSharedMemorySize, SMEM_BYTES);

    gru_init_kernel<<<1024, 256>>>(out, x);
    gru_main_kernel<<<NCTA, NTHREADS, SMEM_BYTES>>>(
        x, gt, W_ih, W_hh, b_ih, b_hh, W_dec, b_dec, out);
}